// round 17
// baseline (speedup 1.0000x reference)
#include <cuda_runtime.h>
#include <cuda_fp16.h>

// Problem constants (fixed shapes from reference)
#define VV 100000
#define DD 64
#define BB 4096
#define LL 50
#define KK 3
#define NBAGS (BB * (2 + KK))   // 20480
#define MAX_NORM 20.0f

#define BAG_CTAS 1184            // 148 SMs * 8 resident CTAs -> exactly one wave

// Renormed embedding table in fp16 (12.8 MB).
__device__ __half d_table[VV * DD];

// Kernel 1: renorm rows. 8 lanes per row; each lane reads 8 floats (2x float4),
// reduces norm across 8 lanes, writes 8 halves (uint4, 16 B).
// PDL: triggers the dependent bag_kernel launch once stores are issued; the
// consumer's cudaGridDependencySynchronize() guarantees visibility.
__global__ __launch_bounds__(256) void renorm_kernel(const float* __restrict__ emb) {
    int idx  = blockIdx.x * blockDim.x + threadIdx.x;
    int row  = idx >> 3;
    int lane = threadIdx.x & 7;

    if (row < VV) {
        const float4* e4 = (const float4*)emb;
        float4 v0 = e4[row * 16 + lane * 2 + 0];
        float4 v1 = e4[row * 16 + lane * 2 + 1];

        float ss = v0.x*v0.x + v0.y*v0.y + v0.z*v0.z + v0.w*v0.w
                 + v1.x*v1.x + v1.y*v1.y + v1.z*v1.z + v1.w*v1.w;
        ss += __shfl_xor_sync(0xffffffffu, ss, 1);
        ss += __shfl_xor_sync(0xffffffffu, ss, 2);
        ss += __shfl_xor_sync(0xffffffffu, ss, 4);

        float norm = sqrtf(ss);
        float s = (norm > MAX_NORM) ? (MAX_NORM / norm) : 1.0f;

        __half2 h0 = __floats2half2_rn(v0.x * s, v0.y * s);
        __half2 h1 = __floats2half2_rn(v0.z * s, v0.w * s);
        __half2 h2 = __floats2half2_rn(v1.x * s, v1.y * s);
        __half2 h3 = __floats2half2_rn(v1.z * s, v1.w * s);
        uint4 packed;
        packed.x = *reinterpret_cast<unsigned*>(&h0);
        packed.y = *reinterpret_cast<unsigned*>(&h1);
        packed.z = *reinterpret_cast<unsigned*>(&h2);
        packed.w = *reinterpret_cast<unsigned*>(&h3);
        ((uint4*)d_table)[row * 8 + lane] = packed;
    }

#if __CUDA_ARCH__ >= 900
    cudaTriggerProgrammaticLaunchCompletion();
#endif
}

// Kernel 2: embedding-bag sum. PERSISTENT grid (one wave, 1184 CTAs),
// grid-stride over bags; R7/R12 verified-optimal body (13 fat 4-line uint4
// gathers per bag at 32 regs). PDL: table-independent prologue runs before
// cudaGridDependencySynchronize(); table gathers only after it.
// Bag order matches output tuple flatten: [l (B) | r (B) | neg (B*K)].
__global__ __launch_bounds__(256) void bag_kernel(
    const int* __restrict__ tl,
    const int* __restrict__ tr,
    const int* __restrict__ tn,
    float* __restrict__ out)
{
    int warp  = threadIdx.x >> 5;
    int lane  = threadIdx.x & 31;
    int sub   = lane >> 3;     // token slot 0..3 within an iteration
    int dlane = lane & 7;      // which 16 B of the 128 B row

    const uint4* t4 = (const uint4*)d_table;   // 8 uint4 per row
    const int nwarps = BAG_CTAS * 8;
    int bag0 = blockIdx.x * 8 + warp;

    // Table-independent prologue done; wait for renorm's stores to be visible.
#if __CUDA_ARCH__ >= 900
    cudaGridDependencySynchronize();
#endif

    for (int bag = bag0; bag < NBAGS; bag += nwarps) {
        const int* p;
        if (bag < BB)          p = tl + bag * LL;
        else if (bag < 2 * BB) p = tr + (bag - BB) * LL;
        else                   p = tn + (bag - 2 * BB) * LL;

        float acc[8] = {0.f, 0.f, 0.f, 0.f, 0.f, 0.f, 0.f, 0.f};

        // 12 full iterations of 4 tokens
        #pragma unroll
        for (int t = 0; t < 48; t += 4) {
            int tok = p[t + sub];                  // uniform across 8-lane group
            uint4 v = __ldg(&t4[tok * 8 + dlane]);
            __half2 a = *reinterpret_cast<__half2*>(&v.x);
            __half2 b = *reinterpret_cast<__half2*>(&v.y);
            __half2 c = *reinterpret_cast<__half2*>(&v.z);
            __half2 d = *reinterpret_cast<__half2*>(&v.w);
            float2 fa = __half22float2(a);
            float2 fb = __half22float2(b);
            float2 fc = __half22float2(c);
            float2 fd = __half22float2(d);
            acc[0] += fa.x; acc[1] += fa.y;
            acc[2] += fb.x; acc[3] += fb.y;
            acc[4] += fc.x; acc[5] += fc.y;
            acc[6] += fd.x; acc[7] += fd.y;
        }
        // tail: tokens 48,49 handled by sub 0,1 only
        if (sub < 2) {
            int tok = p[48 + sub];
            uint4 v = __ldg(&t4[tok * 8 + dlane]);
            __half2 a = *reinterpret_cast<__half2*>(&v.x);
            __half2 b = *reinterpret_cast<__half2*>(&v.y);
            __half2 c = *reinterpret_cast<__half2*>(&v.z);
            __half2 d = *reinterpret_cast<__half2*>(&v.w);
            float2 fa = __half22float2(a);
            float2 fb = __half22float2(b);
            float2 fc = __half22float2(c);
            float2 fd = __half22float2(d);
            acc[0] += fa.x; acc[1] += fa.y;
            acc[2] += fb.x; acc[3] += fb.y;
            acc[4] += fc.x; acc[5] += fc.y;
            acc[6] += fd.x; acc[7] += fd.y;
        }

        // Combine the 4 sub-group partials (lane bits 3,4 index sub).
        #pragma unroll
        for (int i = 0; i < 8; ++i) {
            acc[i] += __shfl_xor_sync(0xffffffffu, acc[i], 8);
            acc[i] += __shfl_xor_sync(0xffffffffu, acc[i], 16);
        }

        // acc[i] on this lane = dim dlane*8 + i (replicated across sub).
        // Each lane writes 2 dims -> 256 B/warp contiguous.
        float2 w = make_float2(acc[sub * 2], acc[sub * 2 + 1]);
        ((float2*)out)[bag * 32 + dlane * 4 + sub] = w;
    }
}

extern "C" void kernel_launch(void* const* d_in, const int* in_sizes, int n_in,
                              void* d_out, int out_size) {
    const float* emb = (const float*)d_in[0];
    const int*   tl  = (const int*)d_in[1];
    const int*   tr  = (const int*)d_in[2];
    const int*   tn  = (const int*)d_in[3];
    float*       out = (float*)d_out;

    int renorm_blocks = (VV * 8 + 255) / 256;    // 3125 (32 rows per block)
    renorm_kernel<<<renorm_blocks, 256>>>(emb);

    // Bag launch with programmatic dependent launch: may begin while renorm
    // drains; correctness enforced by cudaGridDependencySynchronize().
    cudaLaunchConfig_t cfg = {};
    cfg.gridDim  = dim3(BAG_CTAS);
    cfg.blockDim = dim3(256);
    cfg.dynamicSmemBytes = 0;
    cfg.stream = 0;
    cudaLaunchAttribute attrs[1];
    attrs[0].id = cudaLaunchAttributeProgrammaticStreamSerialization;
    attrs[0].val.programmaticStreamSerializationAllowed = 1;
    cfg.attrs = attrs;
    cfg.numAttrs = 1;
    cudaLaunchKernelEx(&cfg, bag_kernel, tl, tr, tn, out);
}